// round 14
// baseline (speedup 1.0000x reference)
#include <cuda_runtime.h>
#include <cuda_bf16.h>
#include <cstdint>

#define NN 50000
#define EE 800000
#define DIM 256
#define GD 8   // gather cp.async pipeline depth

// ---- scratch (static device globals; zero-initialized at load) ----
__device__ __nv_bfloat16 d_h[(size_t)NN * DIM];   // 25.6 MB: GEMM output H (bf16)
__device__ uint2 d_hq[(size_t)NN * 32];           // 12.8 MB: H quantized int8 rows
__device__ float d_ws[NN];                        // per-node dinv*scale
__device__ __nv_bfloat16 d_a[(size_t)NN * DIM];   // 25.6 MB: A1 activations (bf16)
__device__ int   d_degi[NN];                      // re-zeroed by k_fill each replay
__device__ float d_dinv[NN];
__device__ float d_mean[DIM];                     // re-zeroed by k_head each replay
__device__ int   d_rowstart[NN + 1];
__device__ int   d_cursor[NN];
__device__ int   d_csr[EE];

// ---------------- degree ----------------
__global__ void k_deg(const int* __restrict__ dst, int E, int* __restrict__ deg) {
    int e = blockIdx.x * blockDim.x + threadIdx.x;
    if (e < E) atomicAdd(&deg[dst[e]], 1);
}

// ---------------- fused scan: rowstart + cursor + dinv ----------------
__global__ void k_scan(const int* __restrict__ deg, int* __restrict__ rowstart,
                       int* __restrict__ cursor, float* __restrict__ dinv, int n) {
    __shared__ int partial[1024];
    int t = threadIdx.x;
    int chunk = (n + 1023) >> 10;
    int beg = t * chunk;
    int end = min(beg + chunk, n);
    int s = 0;
    for (int i = beg; i < end; i++) s += deg[i];
    partial[t] = s;
    __syncthreads();
    for (int off = 1; off < 1024; off <<= 1) {
        int add = (t >= off) ? partial[t - off] : 0;
        __syncthreads();
        partial[t] += add;
        __syncthreads();
    }
    int excl = (t == 0) ? 0 : partial[t - 1];
    for (int i = beg; i < end; i++) {
        rowstart[i] = excl;
        cursor[i] = excl;
        dinv[i] = rsqrtf((float)deg[i] + 1.0f);   // +1 = self loop
        excl += deg[i];
    }
    if (end == n) rowstart[n] = excl;
}

// ---------------- CSR fill (+ re-zero degi for the next graph replay) ----------------
__global__ void k_fill(const int* __restrict__ src, const int* __restrict__ dst,
                       int* __restrict__ cursor, int* __restrict__ csr, int E,
                       int* __restrict__ degi, int n) {
    int e = blockIdx.x * blockDim.x + threadIdx.x;
    if (e < n) degi[e] = 0;   // dead after k_scan; zero for next replay
    if (e < E) {
        int pos = atomicAdd(&cursor[dst[e]], 1);
        csr[pos] = src[e];
    }
}

// ---------------- cp.async helpers ----------------
__device__ __forceinline__ void cp_async16(void* dst, const void* src, int sbytes) {
    unsigned d = (unsigned)__cvta_generic_to_shared(dst);
    asm volatile("cp.async.cg.shared.global [%0], [%1], 16, %2;"
                 :: "r"(d), "l"(src), "r"(sbytes));
}
__device__ __forceinline__ void cp_async8(void* dst, const void* src) {
    unsigned d = (unsigned)__cvta_generic_to_shared(dst);
    asm volatile("cp.async.ca.shared.global [%0], [%1], 8;"
                 :: "r"(d), "l"(src));
}
__device__ __forceinline__ void cp_commit() {
    asm volatile("cp.async.commit_group;");
}
template <int N>
__device__ __forceinline__ void cp_wait() {
    asm volatile("cp.async.wait_group %0;" :: "n"(N));
}

__device__ __forceinline__ unsigned f2tf32(float f) {
    unsigned u;
    asm("cvt.rna.tf32.f32 %0, %1;" : "=r"(u) : "f"(f));
    return u;
}

// ---------------- TF32 GEMM (cp.async double-buffered), bf16 output ----------------
template <bool BF16IN>
__global__ void __launch_bounds__(256, 2)
k_gemm(const void* __restrict__ Aptr, const float* __restrict__ B,
       __nv_bfloat162* __restrict__ C, int M) {
    extern __shared__ __align__(16) char smem[];
    float* BsBase = (float*)smem;                       // [2][32][132]
    char*  AsBase = smem + 2 * 32 * 132 * 4;            // A tiles

    int t = threadIdx.x;
    int lane = t & 31, wid = t >> 5;
    int wm = wid & 1, wn = wid >> 1;          // warp tile: 64x32
    int gi = lane >> 2, ti = lane & 3;
    int m0 = blockIdx.y * 128, n0 = blockIdx.x * 128;

    float acc[4][4][4] = {};

    auto loadTile = [&](int st, int k0) {
        float* Bs = BsBase + st * 32 * 132;
        #pragma unroll
        for (int i = 0; i < 4; i++) {
            int idx = t + i * 256;
            int br = idx >> 5, bc = (idx & 31) * 4;
            cp_async16(Bs + br * 132 + bc,
                       B + (size_t)(k0 + br) * 256 + n0 + bc, 16);
        }
        if (BF16IN) {
            const __nv_bfloat16* A = (const __nv_bfloat16*)Aptr;
            __nv_bfloat16* As = (__nv_bfloat16*)(AsBase + st * 128 * 80);
            #pragma unroll
            for (int i = 0; i < 2; i++) {
                int idx = t + i * 256;
                int ar = idx >> 2, ac = (idx & 3) * 8;
                int row = m0 + ar;
                int rc = min(row, M - 1);
                cp_async16(As + ar * 40 + ac,
                           A + (size_t)rc * 256 + k0 + ac, row < M ? 16 : 0);
            }
        } else {
            const float* A = (const float*)Aptr;
            float* As = (float*)(AsBase + st * 128 * 144);
            #pragma unroll
            for (int i = 0; i < 4; i++) {
                int idx = t + i * 256;
                int ar = idx >> 3, ac = (idx & 7) * 4;
                int row = m0 + ar;
                int rc = min(row, M - 1);
                cp_async16(As + ar * 36 + ac,
                           A + (size_t)rc * 256 + k0 + ac, row < M ? 16 : 0);
            }
        }
    };

    auto compute = [&](int st) {
        const float* Bs = BsBase + st * 32 * 132;
        #pragma unroll
        for (int kk = 0; kk < 4; kk++) {
            int kb = kk * 8;
            unsigned a[4][4], b[4][2];
            #pragma unroll
            for (int mt = 0; mt < 4; mt++) {
                int r = wm * 64 + mt * 16 + gi;
                if (BF16IN) {
                    const __nv_bfloat16* As =
                        (const __nv_bfloat16*)(AsBase + st * 128 * 80);
                    a[mt][0] = __float_as_uint(__bfloat162float(As[r * 40 + kb + ti]));
                    a[mt][1] = __float_as_uint(__bfloat162float(As[(r + 8) * 40 + kb + ti]));
                    a[mt][2] = __float_as_uint(__bfloat162float(As[r * 40 + kb + ti + 4]));
                    a[mt][3] = __float_as_uint(__bfloat162float(As[(r + 8) * 40 + kb + ti + 4]));
                } else {
                    const float* As = (const float*)(AsBase + st * 128 * 144);
                    a[mt][0] = f2tf32(As[r * 36 + kb + ti]);
                    a[mt][1] = f2tf32(As[(r + 8) * 36 + kb + ti]);
                    a[mt][2] = f2tf32(As[r * 36 + kb + ti + 4]);
                    a[mt][3] = f2tf32(As[(r + 8) * 36 + kb + ti + 4]);
                }
            }
            #pragma unroll
            for (int nt = 0; nt < 4; nt++) {
                int cn = wn * 32 + nt * 8 + gi;
                b[nt][0] = f2tf32(Bs[(kb + ti) * 132 + cn]);
                b[nt][1] = f2tf32(Bs[(kb + ti + 4) * 132 + cn]);
            }
            #pragma unroll
            for (int mt = 0; mt < 4; mt++)
                #pragma unroll
                for (int nt = 0; nt < 4; nt++)
                    asm volatile(
                        "mma.sync.aligned.m16n8k8.row.col.f32.tf32.tf32.f32 "
                        "{%0,%1,%2,%3}, {%4,%5,%6,%7}, {%8,%9}, {%0,%1,%2,%3};"
                        : "+f"(acc[mt][nt][0]), "+f"(acc[mt][nt][1]),
                          "+f"(acc[mt][nt][2]), "+f"(acc[mt][nt][3])
                        : "r"(a[mt][0]), "r"(a[mt][1]), "r"(a[mt][2]), "r"(a[mt][3]),
                          "r"(b[nt][0]), "r"(b[nt][1]));
        }
    };

    loadTile(0, 0);
    cp_commit();
    #pragma unroll
    for (int i = 0; i < 8; i++) {
        if (i + 1 < 8) { loadTile((i + 1) & 1, (i + 1) * 32); cp_commit(); }
        if (i + 1 < 8) cp_wait<1>(); else cp_wait<0>();
        __syncthreads();
        compute(i & 1);
        __syncthreads();
    }

    #pragma unroll
    for (int mt = 0; mt < 4; mt++)
        #pragma unroll
        for (int nt = 0; nt < 4; nt++) {
            int row = m0 + wm * 64 + mt * 16 + gi;
            int pc = n0 / 2 + wn * 16 + nt * 4 + ti;
            if (row < M)
                C[(size_t)row * 128 + pc] =
                    __floats2bfloat162_rn(acc[mt][nt][0], acc[mt][nt][1]);
            if (row + 8 < M)
                C[(size_t)(row + 8) * 128 + pc] =
                    __floats2bfloat162_rn(acc[mt][nt][2], acc[mt][nt][3]);
        }
}

// ---------------- quantize: bf16 H rows -> int8 rows + ws = dinv*scale ----------------
__global__ void k_quant(const uint4* __restrict__ H, const float* __restrict__ dinv,
                        uint2* __restrict__ Hq, float* __restrict__ ws, int n) {
    int node = blockIdx.x * 8 + (threadIdx.x >> 5);
    if (node >= n) return;
    int lane = threadIdx.x & 31;
    uint4 v = H[(size_t)node * 32 + lane];
    const __nv_bfloat162* p = (const __nv_bfloat162*)&v;
    float f[8];
    #pragma unroll
    for (int j = 0; j < 4; j++) {
        float2 t2 = __bfloat1622float2(p[j]);
        f[2 * j] = t2.x; f[2 * j + 1] = t2.y;
    }
    float m = 0.f;
    #pragma unroll
    for (int j = 0; j < 8; j++) m = fmaxf(m, fabsf(f[j]));
    #pragma unroll
    for (int o = 16; o; o >>= 1)
        m = fmaxf(m, __shfl_xor_sync(0xffffffffu, m, o));
    float inv = (m > 0.f) ? 127.f / m : 0.f;
    int q[8];
    #pragma unroll
    for (int j = 0; j < 8; j++) q[j] = __float2int_rn(f[j] * inv);
    uint2 packed;
    packed.x = (q[0] & 0xff) | ((q[1] & 0xff) << 8) |
               ((q[2] & 0xff) << 16) | ((q[3] & 0xff) << 24);
    packed.y = (q[4] & 0xff) | ((q[5] & 0xff) << 8) |
               ((q[6] & 0xff) << 16) | ((q[7] & 0xff) << 24);
    Hq[(size_t)node * 32 + lane] = packed;
    if (lane == 0) ws[node] = dinv[node] * (m * (1.f / 127.f));
}

// ---- int8 row decode + fp32 fma ----
__device__ __forceinline__ void i8_fma(uint2 v, float w, float* acc) {
    int x = (int)v.x, y = (int)v.y;
    acc[0] = fmaf(w, (float)((x << 24) >> 24), acc[0]);
    acc[1] = fmaf(w, (float)((x << 16) >> 24), acc[1]);
    acc[2] = fmaf(w, (float)((x << 8)  >> 24), acc[2]);
    acc[3] = fmaf(w, (float)( x        >> 24), acc[3]);
    acc[4] = fmaf(w, (float)((y << 24) >> 24), acc[4]);
    acc[5] = fmaf(w, (float)((y << 16) >> 24), acc[5]);
    acc[6] = fmaf(w, (float)((y << 8)  >> 24), acc[6]);
    acc[7] = fmaf(w, (float)( y        >> 24), acc[7]);
}

// ---- pipelined gather core: cp.async ring (depth GD), shfl-batched indices ----
__device__ __forceinline__ void gather_node_pipe(const uint2* __restrict__ Hq,
        const float* __restrict__ ws,
        const int* __restrict__ rowstart, const int* __restrict__ csr,
        const float* __restrict__ bias,
        int node, int lane, float di, char* ring, float* res) {
    int r0 = rowstart[node], r1 = rowstart[node + 1];
    float acc[8] = {};
    i8_fma(Hq[(size_t)node * 32 + lane], ws[node], acc);   // self loop (direct)
    for (int base = r0; base < r1; base += 32) {
        int cnt = min(32, r1 - base);
        int sidx = node; float w = 0.f;
        if (base + lane < r1) { sidx = csr[base + lane]; w = ws[sidx]; }
        int pro = min(GD, cnt);
        for (int j = 0; j < pro; j++) {
            int s = __shfl_sync(0xffffffffu, sidx, j);
            cp_async8(ring + j * 256 + lane * 8,
                      (const char*)(Hq + (size_t)s * 32 + lane));
            cp_commit();
        }
        int tailStart = (cnt > GD) ? (cnt - GD) : 0;
        int j = 0;
        for (; j < tailStart; j++) {
            cp_wait<GD - 1>();               // load j complete
            uint2 v = *(const uint2*)(ring + (j & (GD - 1)) * 256 + lane * 8);
            float wj = __shfl_sync(0xffffffffu, w, j);
            i8_fma(v, wj, acc);
            int s = __shfl_sync(0xffffffffu, sidx, j + GD);
            cp_async8(ring + (j & (GD - 1)) * 256 + lane * 8,
                      (const char*)(Hq + (size_t)s * 32 + lane));
            cp_commit();
        }
        cp_wait<0>();                        // drain remaining
        for (; j < cnt; j++) {
            uint2 v = *(const uint2*)(ring + (j & (GD - 1)) * 256 + lane * 8);
            float wj = __shfl_sync(0xffffffffu, w, j);
            i8_fma(v, wj, acc);
        }
    }
    float4 b0 = *(const float4*)(bias + lane * 8);
    float4 b1 = *(const float4*)(bias + lane * 8 + 4);
    float bb[8] = {b0.x, b0.y, b0.z, b0.w, b1.x, b1.y, b1.z, b1.w};
    #pragma unroll
    for (int jj = 0; jj < 8; jj++)
        res[jj] = fmaxf(fmaf(di, acc[jj], bb[jj]), 0.f);
}

// ---------------- gather 1: write bf16 activations ----------------
__global__ void k_gather1(const uint2* __restrict__ Hq, const float* __restrict__ ws,
                          uint4* __restrict__ out,
                          const int* __restrict__ rowstart, const int* __restrict__ csr,
                          const float* __restrict__ dinv,
                          const float* __restrict__ bias, int n) {
    __shared__ char ring[8][GD * 256];
    int wid = threadIdx.x >> 5;
    int node = blockIdx.x * 8 + wid;
    if (node >= n) return;
    int lane = threadIdx.x & 31;
    float res[8];
    gather_node_pipe(Hq, ws, rowstart, csr, bias, node, lane, dinv[node],
                     ring[wid], res);
    __nv_bfloat162 r[4];
    #pragma unroll
    for (int j = 0; j < 4; j++)
        r[j] = __floats2bfloat162_rn(res[2 * j], res[2 * j + 1]);
    out[(size_t)node * 32 + lane] = *(uint4*)r;
}

// ---------------- gather 2: reduce directly into mean ----------------
__global__ void k_gather2(const uint2* __restrict__ Hq, const float* __restrict__ ws,
                          const int* __restrict__ rowstart, const int* __restrict__ csr,
                          const float* __restrict__ dinv,
                          const float* __restrict__ bias,
                          float* __restrict__ mean, int n) {
    __shared__ char ring[8][GD * 256];
    __shared__ float sm[8][256];
    int wid = threadIdx.x >> 5;
    int lane = threadIdx.x & 31;
    int node = blockIdx.x * 8 + wid;
    float res[8] = {};
    if (node < n)
        gather_node_pipe(Hq, ws, rowstart, csr, bias, node, lane, dinv[node],
                         ring[wid], res);
    #pragma unroll
    for (int j = 0; j < 8; j++) sm[wid][lane * 8 + j] = res[j];
    __syncthreads();
    int c = threadIdx.x;
    float s = 0.f;
    #pragma unroll
    for (int w = 0; w < 8; w++) s += sm[w][c];
    atomicAdd(&mean[c], s);
}

// ---------------- MLP head (+ re-zero mean for the next graph replay) ----------------
__global__ void k_head(float* __restrict__ mean,
                       const float* __restrict__ fcW1, const float* __restrict__ fcb1,
                       const float* __restrict__ fcW2, const float* __restrict__ fcb2,
                       const float* __restrict__ fcW3, const float* __restrict__ fcb3,
                       float* __restrict__ out, int n) {
    __shared__ float g[256], h[256];
    int j = threadIdx.x;
    g[j] = fmaxf(mean[j] * (1.0f / (float)n), 0.f);
    mean[j] = 0.f;   // dead after this read; zero for next replay
    __syncthreads();
    float s = fcb1[j];
    #pragma unroll 8
    for (int i = 0; i < 256; i++) s = fmaf(g[i], fcW1[i * 256 + j], s);
    h[j] = fmaxf(s, 0.f);
    __syncthreads();
    s = fcb2[j];
    #pragma unroll 8
    for (int i = 0; i < 256; i++) s = fmaf(h[i], fcW2[i * 256 + j], s);
    float g2 = fmaxf(s, 0.f);
    __syncthreads();
    g[j] = g2;
    __syncthreads();
    if (j < 64) {
        s = fcb3[j];
        #pragma unroll 8
        for (int i = 0; i < 256; i++) s = fmaf(g[i], fcW3[i * 64 + j], s);
        out[j] = s;
    }
}

extern "C" void kernel_launch(void* const* d_in, const int* in_sizes, int n_in,
                              void* d_out, int out_size) {
    const float* x    = (const float*)d_in[0];
    const int*   ei   = (const int*)  d_in[1];   // [2, E] int32
    const float* W1   = (const float*)d_in[2];
    const float* b1   = (const float*)d_in[3];
    const float* W2   = (const float*)d_in[4];
    const float* b2   = (const float*)d_in[5];
    const float* fcW1 = (const float*)d_in[6];
    const float* fcb1 = (const float*)d_in[7];
    const float* fcW2 = (const float*)d_in[8];
    const float* fcb2 = (const float*)d_in[9];
    const float* fcW3 = (const float*)d_in[10];
    const float* fcb3 = (const float*)d_in[11];
    float* out = (float*)d_out;

    int E = in_sizes[1] / 2;
    int N = in_sizes[0] / DIM;
    const int* src = ei;
    const int* dst = ei + E;

    __nv_bfloat16 *hbuf, *abuf;
    uint2* hq;
    float *dinv, *mean, *ws;
    int *degi, *rowstart, *cursor, *csr;
    cudaGetSymbolAddress((void**)&hbuf, d_h);
    cudaGetSymbolAddress((void**)&hq,   d_hq);
    cudaGetSymbolAddress((void**)&ws,   d_ws);
    cudaGetSymbolAddress((void**)&abuf, d_a);
    cudaGetSymbolAddress((void**)&degi, d_degi);
    cudaGetSymbolAddress((void**)&dinv, d_dinv);
    cudaGetSymbolAddress((void**)&mean, d_mean);
    cudaGetSymbolAddress((void**)&rowstart, d_rowstart);
    cudaGetSymbolAddress((void**)&cursor, d_cursor);
    cudaGetSymbolAddress((void**)&csr, d_csr);

    // dynamic smem opt-in for the GEMMs
    const int SMEM32 = 2 * 32 * 132 * 4 + 2 * 128 * 144;  // 70656
    const int SMEM16 = 2 * 32 * 132 * 4 + 2 * 128 * 80;   // 54272
    cudaFuncSetAttribute(k_gemm<false>,
                         cudaFuncAttributeMaxDynamicSharedMemorySize, SMEM32);
    cudaFuncSetAttribute(k_gemm<true>,
                         cudaFuncAttributeMaxDynamicSharedMemorySize, SMEM16);

    // side stream + events (created once; host-side resources only)
    static cudaStream_t s_side = nullptr;
    static cudaEvent_t ev_fork = nullptr, ev_join = nullptr;
    if (s_side == nullptr) {
        cudaStreamCreateWithFlags(&s_side, cudaStreamNonBlocking);
        cudaEventCreateWithFlags(&ev_fork, cudaEventDisableTiming);
        cudaEventCreateWithFlags(&ev_join, cudaEventDisableTiming);
    }

    dim3 gg(2, (N + 127) / 128);
    unsigned gblocks = (unsigned)((N + 7) / 8);

    // Submission order: my 4th kernel = k_gemm<false> (ncu -s 5 -c 1 slot).
    cudaEventRecord(ev_fork, 0);
    cudaStreamWaitEvent(s_side, ev_fork, 0);
    k_deg<<<(E + 255) / 256, 256, 0, s_side>>>(dst, E, degi);            // 1 (side)
    k_scan<<<1, 1024, 0, s_side>>>(degi, rowstart, cursor, dinv, N);     // 2 (side)
    k_fill<<<(E + 255) / 256, 256, 0, s_side>>>(src, dst, cursor, csr, E,
                                                degi, N);                // 3 (side)
    cudaEventRecord(ev_join, s_side);
    k_gemm<false><<<gg, 256, SMEM32>>>(x, W1, (__nv_bfloat162*)hbuf, N); // 4 (main) <- ncu

    // join: quant needs dinv; gathers need CSR
    cudaStreamWaitEvent(0, ev_join, 0);

    // ---- layer 1: quantize + aggregate ----
    k_quant<<<gblocks, 256>>>((const uint4*)hbuf, dinv, hq, ws, N);
    k_gather1<<<gblocks, 256>>>(hq, ws, (uint4*)abuf, rowstart, csr, dinv, b1, N);
    // ---- layer 2: GEMM + quantize + aggregate(mean fused) ----
    k_gemm<true><<<gg, 256, SMEM16>>>(abuf, W2, (__nv_bfloat162*)hbuf, N);
    k_quant<<<gblocks, 256>>>((const uint4*)hbuf, dinv, hq, ws, N);
    k_gather2<<<gblocks, 256>>>(hq, ws, rowstart, csr, dinv, b2, mean, N);
    // ---- head ----
    k_head<<<1, 256>>>(mean, fcW1, fcb1, fcW2, fcb2, fcW3, fcb3, out, N);
}

// round 16
// speedup vs baseline: 1.0166x; 1.0166x over previous
#include <cuda_runtime.h>
#include <cuda_bf16.h>
#include <cstdint>

#define NN 50000
#define EE 800000
#define DIM 256
#define CH 2          // pipeline chunks
#define CHROWS 25088  // rows per chunk (multiple of 128 and 8)

// ---- scratch (static device globals; zero-initialized at load) ----
__device__ __nv_bfloat16 d_h[(size_t)NN * DIM];   // 25.6 MB: GEMM output H (bf16)
__device__ uint2 d_hq1[(size_t)NN * 32];          // 12.8 MB: layer-1 int8 rows
__device__ uint2 d_hq2[(size_t)NN * 32];          // 12.8 MB: layer-2 int8 rows
__device__ float d_ws1[NN];                       // layer-1 dinv*scale
__device__ float d_ws2[NN];                       // layer-2 dinv*scale
__device__ __nv_bfloat16 d_a[(size_t)NN * DIM];   // 25.6 MB: A1 activations (bf16)
__device__ int   d_degi[NN];                      // re-zeroed by k_fill each replay
__device__ float d_dinv[NN];
__device__ float d_mean[DIM];                     // re-zeroed by k_head each replay
__device__ int   d_rowstart[NN + 1];
__device__ int   d_cursor[NN];
__device__ int   d_csr[EE];

// ---------------- degree ----------------
__global__ void k_deg(const int* __restrict__ dst, int E, int* __restrict__ deg) {
    int e = blockIdx.x * blockDim.x + threadIdx.x;
    if (e < E) atomicAdd(&deg[dst[e]], 1);
}

// ---------------- fused scan: rowstart + cursor + dinv ----------------
__global__ void k_scan(const int* __restrict__ deg, int* __restrict__ rowstart,
                       int* __restrict__ cursor, float* __restrict__ dinv, int n) {
    __shared__ int partial[1024];
    int t = threadIdx.x;
    int chunk = (n + 1023) >> 10;
    int beg = t * chunk;
    int end = min(beg + chunk, n);
    int s = 0;
    for (int i = beg; i < end; i++) s += deg[i];
    partial[t] = s;
    __syncthreads();
    for (int off = 1; off < 1024; off <<= 1) {
        int add = (t >= off) ? partial[t - off] : 0;
        __syncthreads();
        partial[t] += add;
        __syncthreads();
    }
    int excl = (t == 0) ? 0 : partial[t - 1];
    for (int i = beg; i < end; i++) {
        rowstart[i] = excl;
        cursor[i] = excl;
        dinv[i] = rsqrtf((float)deg[i] + 1.0f);   // +1 = self loop
        excl += deg[i];
    }
    if (end == n) rowstart[n] = excl;
}

// ---------------- CSR fill (+ re-zero degi for the next graph replay) ----------------
__global__ void k_fill(const int* __restrict__ src, const int* __restrict__ dst,
                       int* __restrict__ cursor, int* __restrict__ csr, int E,
                       int* __restrict__ degi, int n) {
    int e = blockIdx.x * blockDim.x + threadIdx.x;
    if (e < n) degi[e] = 0;   // dead after k_scan; zero for next replay
    if (e < E) {
        int pos = atomicAdd(&cursor[dst[e]], 1);
        csr[pos] = src[e];
    }
}

// ---------------- cp.async helpers ----------------
__device__ __forceinline__ void cp_async16(void* dst, const void* src, int sbytes) {
    unsigned d = (unsigned)__cvta_generic_to_shared(dst);
    asm volatile("cp.async.cg.shared.global [%0], [%1], 16, %2;"
                 :: "r"(d), "l"(src), "r"(sbytes));
}
__device__ __forceinline__ void cp_commit() {
    asm volatile("cp.async.commit_group;");
}
template <int N>
__device__ __forceinline__ void cp_wait() {
    asm volatile("cp.async.wait_group %0;" :: "n"(N));
}

__device__ __forceinline__ unsigned f2tf32(float f) {
    unsigned u;
    asm("cvt.rna.tf32.f32 %0, %1;" : "=r"(u) : "f"(f));
    return u;
}

// ---------------- TF32 GEMM (cp.async double-buffered), bf16 output, row-offset ----
template <bool BF16IN>
__global__ void __launch_bounds__(256, 2)
k_gemm(const void* __restrict__ Aptr, const float* __restrict__ B,
       __nv_bfloat162* __restrict__ C, int M, int rowOff) {
    extern __shared__ __align__(16) char smem[];
    float* BsBase = (float*)smem;                       // [2][32][132]
    char*  AsBase = smem + 2 * 32 * 132 * 4;            // A tiles

    int t = threadIdx.x;
    int lane = t & 31, wid = t >> 5;
    int wm = wid & 1, wn = wid >> 1;          // warp tile: 64x32
    int gi = lane >> 2, ti = lane & 3;
    int m0 = rowOff + blockIdx.y * 128, n0 = blockIdx.x * 128;

    float acc[4][4][4] = {};

    auto loadTile = [&](int st, int k0) {
        float* Bs = BsBase + st * 32 * 132;
        #pragma unroll
        for (int i = 0; i < 4; i++) {
            int idx = t + i * 256;
            int br = idx >> 5, bc = (idx & 31) * 4;
            cp_async16(Bs + br * 132 + bc,
                       B + (size_t)(k0 + br) * 256 + n0 + bc, 16);
        }
        if (BF16IN) {
            const __nv_bfloat16* A = (const __nv_bfloat16*)Aptr;
            __nv_bfloat16* As = (__nv_bfloat16*)(AsBase + st * 128 * 80);
            #pragma unroll
            for (int i = 0; i < 2; i++) {
                int idx = t + i * 256;
                int ar = idx >> 2, ac = (idx & 3) * 8;
                int row = m0 + ar;
                int rc = min(row, M - 1);
                cp_async16(As + ar * 40 + ac,
                           A + (size_t)rc * 256 + k0 + ac, row < M ? 16 : 0);
            }
        } else {
            const float* A = (const float*)Aptr;
            float* As = (float*)(AsBase + st * 128 * 144);
            #pragma unroll
            for (int i = 0; i < 4; i++) {
                int idx = t + i * 256;
                int ar = idx >> 3, ac = (idx & 7) * 4;
                int row = m0 + ar;
                int rc = min(row, M - 1);
                cp_async16(As + ar * 36 + ac,
                           A + (size_t)rc * 256 + k0 + ac, row < M ? 16 : 0);
            }
        }
    };

    auto compute = [&](int st) {
        const float* Bs = BsBase + st * 32 * 132;
        #pragma unroll
        for (int kk = 0; kk < 4; kk++) {
            int kb = kk * 8;
            unsigned a[4][4], b[4][2];
            #pragma unroll
            for (int mt = 0; mt < 4; mt++) {
                int r = wm * 64 + mt * 16 + gi;
                if (BF16IN) {
                    const __nv_bfloat16* As =
                        (const __nv_bfloat16*)(AsBase + st * 128 * 80);
                    a[mt][0] = __float_as_uint(__bfloat162float(As[r * 40 + kb + ti]));
                    a[mt][1] = __float_as_uint(__bfloat162float(As[(r + 8) * 40 + kb + ti]));
                    a[mt][2] = __float_as_uint(__bfloat162float(As[r * 40 + kb + ti + 4]));
                    a[mt][3] = __float_as_uint(__bfloat162float(As[(r + 8) * 40 + kb + ti + 4]));
                } else {
                    const float* As = (const float*)(AsBase + st * 128 * 144);
                    a[mt][0] = f2tf32(As[r * 36 + kb + ti]);
                    a[mt][1] = f2tf32(As[(r + 8) * 36 + kb + ti]);
                    a[mt][2] = f2tf32(As[r * 36 + kb + ti + 4]);
                    a[mt][3] = f2tf32(As[(r + 8) * 36 + kb + ti + 4]);
                }
            }
            #pragma unroll
            for (int nt = 0; nt < 4; nt++) {
                int cn = wn * 32 + nt * 8 + gi;
                b[nt][0] = f2tf32(Bs[(kb + ti) * 132 + cn]);
                b[nt][1] = f2tf32(Bs[(kb + ti + 4) * 132 + cn]);
            }
            #pragma unroll
            for (int mt = 0; mt < 4; mt++)
                #pragma unroll
                for (int nt = 0; nt < 4; nt++)
                    asm volatile(
                        "mma.sync.aligned.m16n8k8.row.col.f32.tf32.tf32.f32 "
                        "{%0,%1,%2,%3}, {%4,%5,%6,%7}, {%8,%9}, {%0,%1,%2,%3};"
                        : "+f"(acc[mt][nt][0]), "+f"(acc[mt][nt][1]),
                          "+f"(acc[mt][nt][2]), "+f"(acc[mt][nt][3])
                        : "r"(a[mt][0]), "r"(a[mt][1]), "r"(a[mt][2]), "r"(a[mt][3]),
                          "r"(b[nt][0]), "r"(b[nt][1]));
        }
    };

    loadTile(0, 0);
    cp_commit();
    #pragma unroll
    for (int i = 0; i < 8; i++) {
        if (i + 1 < 8) { loadTile((i + 1) & 1, (i + 1) * 32); cp_commit(); }
        if (i + 1 < 8) cp_wait<1>(); else cp_wait<0>();
        __syncthreads();
        compute(i & 1);
        __syncthreads();
    }

    #pragma unroll
    for (int mt = 0; mt < 4; mt++)
        #pragma unroll
        for (int nt = 0; nt < 4; nt++) {
            int row = m0 + wm * 64 + mt * 16 + gi;
            int pc = n0 / 2 + wn * 16 + nt * 4 + ti;
            if (row < M)
                C[(size_t)row * 128 + pc] =
                    __floats2bfloat162_rn(acc[mt][nt][0], acc[mt][nt][1]);
            if (row + 8 < M)
                C[(size_t)(row + 8) * 128 + pc] =
                    __floats2bfloat162_rn(acc[mt][nt][2], acc[mt][nt][3]);
        }
}

// ---------------- quantize (chunked): bf16 H rows -> int8 rows + ws ----------------
__global__ void k_quant(const uint4* __restrict__ H, const float* __restrict__ dinv,
                        uint2* __restrict__ Hq, float* __restrict__ ws,
                        int nodeOff, int nodeEnd) {
    int node = nodeOff + blockIdx.x * 8 + (threadIdx.x >> 5);
    if (node >= nodeEnd) return;
    int lane = threadIdx.x & 31;
    uint4 v = H[(size_t)node * 32 + lane];
    const __nv_bfloat162* p = (const __nv_bfloat162*)&v;
    float f[8];
    #pragma unroll
    for (int j = 0; j < 4; j++) {
        float2 t2 = __bfloat1622float2(p[j]);
        f[2 * j] = t2.x; f[2 * j + 1] = t2.y;
    }
    float m = 0.f;
    #pragma unroll
    for (int j = 0; j < 8; j++) m = fmaxf(m, fabsf(f[j]));
    #pragma unroll
    for (int o = 16; o; o >>= 1)
        m = fmaxf(m, __shfl_xor_sync(0xffffffffu, m, o));
    float inv = (m > 0.f) ? 127.f / m : 0.f;
    int q[8];
    #pragma unroll
    for (int j = 0; j < 8; j++) q[j] = __float2int_rn(f[j] * inv);
    uint2 packed;
    packed.x = (q[0] & 0xff) | ((q[1] & 0xff) << 8) |
               ((q[2] & 0xff) << 16) | ((q[3] & 0xff) << 24);
    packed.y = (q[4] & 0xff) | ((q[5] & 0xff) << 8) |
               ((q[6] & 0xff) << 16) | ((q[7] & 0xff) << 24);
    Hq[(size_t)node * 32 + lane] = packed;
    if (lane == 0) ws[node] = dinv[node] * (m * (1.f / 127.f));
}

// ---- int8 row decode + fp32 fma (measured-best form) ----
__device__ __forceinline__ void i8_fma(uint2 v, float w, float* acc) {
    int x = (int)v.x, y = (int)v.y;
    acc[0] = fmaf(w, (float)((x << 24) >> 24), acc[0]);
    acc[1] = fmaf(w, (float)((x << 16) >> 24), acc[1]);
    acc[2] = fmaf(w, (float)((x << 8)  >> 24), acc[2]);
    acc[3] = fmaf(w, (float)( x        >> 24), acc[3]);
    acc[4] = fmaf(w, (float)((y << 24) >> 24), acc[4]);
    acc[5] = fmaf(w, (float)((y << 16) >> 24), acc[5]);
    acc[6] = fmaf(w, (float)((y << 8)  >> 24), acc[6]);
    acc[7] = fmaf(w, (float)( y        >> 24), acc[7]);
}

__device__ __forceinline__ void gather_node(const uint2* __restrict__ Hq,
        const float* __restrict__ ws,
        const int* __restrict__ rowstart, const int* __restrict__ csr,
        const float* __restrict__ bias,
        int node, int lane, float di, float* res) {
    int r0 = rowstart[node], r1 = rowstart[node + 1];
    float acc[8] = {};
    i8_fma(Hq[(size_t)node * 32 + lane], ws[node], acc);   // self loop
    int e = r0;
    for (; e + 3 < r1; e += 4) {
        int s0 = csr[e], s1 = csr[e + 1], s2 = csr[e + 2], s3 = csr[e + 3];
        float w0 = ws[s0], w1 = ws[s1], w2 = ws[s2], w3 = ws[s3];
        uint2 v0 = Hq[(size_t)s0 * 32 + lane];
        uint2 v1 = Hq[(size_t)s1 * 32 + lane];
        uint2 v2 = Hq[(size_t)s2 * 32 + lane];
        uint2 v3 = Hq[(size_t)s3 * 32 + lane];
        i8_fma(v0, w0, acc);
        i8_fma(v1, w1, acc);
        i8_fma(v2, w2, acc);
        i8_fma(v3, w3, acc);
    }
    for (; e < r1; e++) {
        int s0 = csr[e];
        i8_fma(Hq[(size_t)s0 * 32 + lane], ws[s0], acc);
    }
    float4 b0 = *(const float4*)(bias + lane * 8);
    float4 b1 = *(const float4*)(bias + lane * 8 + 4);
    float bb[8] = {b0.x, b0.y, b0.z, b0.w, b1.x, b1.y, b1.z, b1.w};
    #pragma unroll
    for (int j = 0; j < 8; j++)
        res[j] = fmaxf(fmaf(di, acc[j], bb[j]), 0.f);
}

// ---------------- gather 1 (chunked): write bf16 activations ----------------
__global__ void k_gather1(const uint2* __restrict__ Hq, const float* __restrict__ ws,
                          uint4* __restrict__ out,
                          const int* __restrict__ rowstart, const int* __restrict__ csr,
                          const float* __restrict__ dinv,
                          const float* __restrict__ bias,
                          int nodeOff, int nodeEnd) {
    int node = nodeOff + blockIdx.x * 8 + (threadIdx.x >> 5);
    if (node >= nodeEnd) return;
    int lane = threadIdx.x & 31;
    float res[8];
    gather_node(Hq, ws, rowstart, csr, bias, node, lane, dinv[node], res);
    __nv_bfloat162 r[4];
    #pragma unroll
    for (int j = 0; j < 4; j++)
        r[j] = __floats2bfloat162_rn(res[2 * j], res[2 * j + 1]);
    out[(size_t)node * 32 + lane] = *(uint4*)r;
}

// ---------------- gather 2: reduce directly into mean ----------------
__global__ void k_gather2(const uint2* __restrict__ Hq, const float* __restrict__ ws,
                          const int* __restrict__ rowstart, const int* __restrict__ csr,
                          const float* __restrict__ dinv,
                          const float* __restrict__ bias,
                          float* __restrict__ mean, int n) {
    __shared__ float sm[8][256];
    int warp = threadIdx.x >> 5;
    int lane = threadIdx.x & 31;
    int node = blockIdx.x * 8 + warp;
    float res[8] = {};
    if (node < n)
        gather_node(Hq, ws, rowstart, csr, bias, node, lane, dinv[node], res);
    #pragma unroll
    for (int j = 0; j < 8; j++) sm[warp][lane * 8 + j] = res[j];
    __syncthreads();
    int c = threadIdx.x;
    float s = 0.f;
    #pragma unroll
    for (int w = 0; w < 8; w++) s += sm[w][c];
    atomicAdd(&mean[c], s);
}

// ---------------- MLP head (+ re-zero mean for the next graph replay) ----------------
__global__ void k_head(float* __restrict__ mean,
                       const float* __restrict__ fcW1, const float* __restrict__ fcb1,
                       const float* __restrict__ fcW2, const float* __restrict__ fcb2,
                       const float* __restrict__ fcW3, const float* __restrict__ fcb3,
                       float* __restrict__ out, int n) {
    __shared__ float g[256], h[256];
    int j = threadIdx.x;
    g[j] = fmaxf(mean[j] * (1.0f / (float)n), 0.f);
    mean[j] = 0.f;   // dead after this read; zero for next replay
    __syncthreads();
    float s = fcb1[j];
    #pragma unroll 8
    for (int i = 0; i < 256; i++) s = fmaf(g[i], fcW1[i * 256 + j], s);
    h[j] = fmaxf(s, 0.f);
    __syncthreads();
    s = fcb2[j];
    #pragma unroll 8
    for (int i = 0; i < 256; i++) s = fmaf(h[i], fcW2[i * 256 + j], s);
    float g2 = fmaxf(s, 0.f);
    __syncthreads();
    g[j] = g2;
    __syncthreads();
    if (j < 64) {
        s = fcb3[j];
        #pragma unroll 8
        for (int i = 0; i < 256; i++) s = fmaf(g[i], fcW3[i * 64 + j], s);
        out[j] = s;
    }
}

extern "C" void kernel_launch(void* const* d_in, const int* in_sizes, int n_in,
                              void* d_out, int out_size) {
    const float* x    = (const float*)d_in[0];
    const int*   ei   = (const int*)  d_in[1];   // [2, E] int32
    const float* W1   = (const float*)d_in[2];
    const float* b1   = (const float*)d_in[3];
    const float* W2   = (const float*)d_in[4];
    const float* b2   = (const float*)d_in[5];
    const float* fcW1 = (const float*)d_in[6];
    const float* fcb1 = (const float*)d_in[7];
    const float* fcW2 = (const float*)d_in[8];
    const float* fcb2 = (const float*)d_in[9];
    const float* fcW3 = (const float*)d_in[10];
    const float* fcb3 = (const float*)d_in[11];
    float* out = (float*)d_out;

    int E = in_sizes[1] / 2;
    int N = in_sizes[0] / DIM;
    const int* src = ei;
    const int* dst = ei + E;

    __nv_bfloat16 *hbuf, *abuf;
    uint2 *hq1, *hq2;
    float *dinv, *mean, *ws1, *ws2;
    int *degi, *rowstart, *cursor, *csr;
    cudaGetSymbolAddress((void**)&hbuf, d_h);
    cudaGetSymbolAddress((void**)&hq1,  d_hq1);
    cudaGetSymbolAddress((void**)&hq2,  d_hq2);
    cudaGetSymbolAddress((void**)&ws1,  d_ws1);
    cudaGetSymbolAddress((void**)&ws2,  d_ws2);
    cudaGetSymbolAddress((void**)&abuf, d_a);
    cudaGetSymbolAddress((void**)&degi, d_degi);
    cudaGetSymbolAddress((void**)&dinv, d_dinv);
    cudaGetSymbolAddress((void**)&mean, d_mean);
    cudaGetSymbolAddress((void**)&rowstart, d_rowstart);
    cudaGetSymbolAddress((void**)&cursor, d_cursor);
    cudaGetSymbolAddress((void**)&csr, d_csr);

    // dynamic smem opt-in for the GEMMs
    const int SMEM32 = 2 * 32 * 132 * 4 + 2 * 128 * 144;  // 70656
    const int SMEM16 = 2 * 32 * 132 * 4 + 2 * 128 * 80;   // 54272
    cudaFuncSetAttribute(k_gemm<false>,
                         cudaFuncAttributeMaxDynamicSharedMemorySize, SMEM32);
    cudaFuncSetAttribute(k_gemm<true>,
                         cudaFuncAttributeMaxDynamicSharedMemorySize, SMEM16);

    // side stream + events (created once; host-side resources only)
    static cudaStream_t s_side = nullptr;
    static cudaEvent_t ev_fork = nullptr, ev_q1 = nullptr, ev_q2 = nullptr;
    static cudaEvent_t evG1[CH], evA1[CH];
    if (s_side == nullptr) {
        cudaStreamCreateWithFlags(&s_side, cudaStreamNonBlocking);
        cudaEventCreateWithFlags(&ev_fork, cudaEventDisableTiming);
        cudaEventCreateWithFlags(&ev_q1, cudaEventDisableTiming);
        cudaEventCreateWithFlags(&ev_q2, cudaEventDisableTiming);
        for (int c = 0; c < CH; c++) {
            cudaEventCreateWithFlags(&evG1[c], cudaEventDisableTiming);
            cudaEventCreateWithFlags(&evA1[c], cudaEventDisableTiming);
        }
    }

    int off[CH + 1];
    for (int c = 0; c <= CH; c++) off[c] = min(N, c * CHROWS);

    // ---- CSR build on side stream ----
    cudaEventRecord(ev_fork, 0);
    cudaStreamWaitEvent(s_side, ev_fork, 0);
    k_deg<<<(E + 255) / 256, 256, 0, s_side>>>(dst, E, degi);
    k_scan<<<1, 1024, 0, s_side>>>(degi, rowstart, cursor, dinv, N);
    k_fill<<<(E + 255) / 256, 256, 0, s_side>>>(src, dst, cursor, csr, E, degi, N);

    // ---- phase 1: gemm1 chunks (main) ∥ quant1 chunks (side) -> hq1/ws1 ----
    for (int c = 0; c < CH; c++) {
        int rows = off[c + 1] - off[c];
        dim3 g(2, (unsigned)((rows + 127) / 128));
        k_gemm<false><<<g, 256, SMEM32>>>(x, W1, (__nv_bfloat162*)hbuf, N, off[c]);
        cudaEventRecord(evG1[c], 0);
        cudaStreamWaitEvent(s_side, evG1[c], 0);
        unsigned qb = (unsigned)((rows + 7) / 8);
        k_quant<<<qb, 256, 0, s_side>>>((const uint4*)hbuf, dinv, hq1, ws1,
                                        off[c], off[c + 1]);
    }
    cudaEventRecord(ev_q1, s_side);
    cudaStreamWaitEvent(0, ev_q1, 0);

    // ---- phase 2: gather1 chunks (main, reads hq1/ws1 only)
    //               ∥ gemm2+quant2 chunks (side, writes hbuf + hq2/ws2 only) ----
    for (int c = 0; c < CH; c++) {
        int rows = off[c + 1] - off[c];
        unsigned gb = (unsigned)((rows + 7) / 8);
        k_gather1<<<gb, 256>>>(hq1, ws1, (uint4*)abuf, rowstart, csr, dinv, b1,
                               off[c], off[c + 1]);
        cudaEventRecord(evA1[c], 0);
        cudaStreamWaitEvent(s_side, evA1[c], 0);
        dim3 g(2, (unsigned)((rows + 127) / 128));
        k_gemm<true><<<g, 256, SMEM16, s_side>>>(abuf, W2, (__nv_bfloat162*)hbuf,
                                                 N, off[c]);
        k_quant<<<gb, 256, 0, s_side>>>((const uint4*)hbuf, dinv, hq2, ws2,
                                        off[c], off[c + 1]);
    }
    cudaEventRecord(ev_q2, s_side);
    cudaStreamWaitEvent(0, ev_q2, 0);

    // ---- gather 2 (full, fused mean, reads hq2/ws2) + head ----
    unsigned gblocks = (unsigned)((N + 7) / 8);
    k_gather2<<<gblocks, 256>>>(hq2, ws2, rowstart, csr, dinv, b2, mean, N);
    k_head<<<1, 256>>>(mean, fcW1, fcb1, fcW2, fcb2, fcW3, fcb3, out, N);
}